// round 1
// baseline (speedup 1.0000x reference)
#include <cuda_runtime.h>

// ---------------- constants ----------------
constexpr int NP = 8 * 32 * 32;            // 8192 positions
constexpr int WTOT = 23592960;             // total conv weights
constexpr int PER_BLK_W = 737280;          // weights per flow block
constexpr int PER_BLK_B = 704;             // biases per flow block

// ---------------- device scratch ----------------
__device__ float g_wt[WTOT];               // transposed weights [conv][k*ic + c][oc]
__device__ float g_mt[32 * 192 * 192];     // transposed mixing mats [blk][c][o]
__device__ float g_Xa[NP * 192];
__device__ float g_Xb[NP * 192];
__device__ float g_T1[NP * 128];
__device__ float g_T2[NP * 128];

// ---------------- weight transform ----------------
// dst-indexed (coalesced writes): dst = blk*PER_BLK_W + start[j] + (k*ic + c)*oc + o
__global__ void k_wt(const float* __restrict__ wf) {
    int idx = blockIdx.x * 256 + threadIdx.x;
    if (idx >= WTOT) return;
    int blk = idx / PER_BLK_W;
    int r = idx - blk * PER_BLK_W;
    const int starts[6] = {0, 110592, 258048, 368640, 479232, 626688};
    int j = 0;
#pragma unroll
    for (int t = 1; t < 6; t++) if (r >= starts[t]) j = t;
    int off = r - starts[j];
    int oc = ((j % 3) == 2) ? 96 : 128;
    int ic = ((j % 3) == 0) ? 96 : 128;
    int o  = off % oc;
    int kc = off / oc;
    int c  = kc % ic;
    int k  = kc / ic;
    g_wt[idx] = wf[blk * PER_BLK_W + starts[j] + (o * ic + c) * 9 + k];
}

// ---------------- mixing matrix transpose ----------------
__global__ void k_mt(const float* __restrict__ m) {
    int idx = blockIdx.x * 256 + threadIdx.x;
    if (idx >= 32 * 36864) return;
    int blk = idx / 36864;
    int r = idx - blk * 36864;
    int c = r / 192;
    int o = r - c * 192;
    g_mt[idx] = m[blk * 36864 + o * 192 + c];
}

// ---------------- normalize + permute + space_to_depth -> NHWC ----------------
__global__ void k_pre(const float* __restrict__ x, const float* __restrict__ mu,
                      const float* __restrict__ sigma, const int* __restrict__ perm) {
    int idx = blockIdx.x * 256 + threadIdx.x;
    if (idx >= NP * 192) return;
    int ch = idx % 192;
    int p = idx / 192;
    int w = p & 31;
    int h = (p >> 5) & 31;
    int b = p >> 10;
    int c = ch >> 6;
    int r = ch & 63;
    int bi = r >> 3;
    int bj = r & 7;
    int flat = (h * 8 + bi) * 256 + (w * 8 + bj);
    int src = perm[c * 65536 + flat];
    g_Xa[idx] = (x[(b * 3 + c) * 65536 + src] - mu[c]) / sigma[c];
}

// ---------------- final NHWC -> NCHW ----------------
__global__ void k_post(const float* __restrict__ X, float* __restrict__ out) {
    int idx = blockIdx.x * 256 + threadIdx.x;
    if (idx >= NP * 192) return;
    int w = idx & 31;
    int h = (idx >> 5) & 31;
    int ch = (idx >> 10) % 192;
    int b = idx / (192 * 1024);
    out[idx] = X[(((b * 32 + h) * 32 + w) * 192) + ch];
}

// ---------------- implicit-GEMM conv (fp32) ----------------
// CTA: 64 positions (2 image rows) x OC outputs. Threads 256: tx=tid&15 -> OC/16
// channels, ty=tid>>4 -> 4 positions. K-tiled by 32 input channels per (ky,kx).
template <int IC, int OC, int KS, bool RELU, bool ADDIN>
__global__ __launch_bounds__(256, 2) void k_conv(
    const float* __restrict__ in, int in_stride,
    const float* __restrict__ wt,
    const float* __restrict__ bias,
    const float* __restrict__ addp, int add_stride,
    float* __restrict__ out, int out_stride)
{
    constexpr int OCT = OC / 16;
    constexpr int NB = (32 * OC) / (4 * 256);   // float4 B-loads per thread
    constexpr int PH = KS / 2;

    __shared__ float As[32][64];
    __shared__ float Bs[32][OC];

    const int tid = threadIdx.x;
    const int tx = tid & 15, ty = tid >> 4;
    const int p0 = blockIdx.x * 64;
    const int b = p0 >> 10;
    const int h0 = (p0 >> 5) & 31;

    const int lpos = tid & 63;      // loader: position within tile
    const int cg = tid >> 6;        // loader: channel group 0..3 (8ch each)
    const int lr = lpos >> 5, lw = lpos & 31;

    float acc[4][OCT];
#pragma unroll
    for (int i = 0; i < 4; i++)
#pragma unroll
        for (int j = 0; j < OCT; j++) acc[i][j] = 0.f;

    for (int ky = 0; ky < KS; ky++) {
        for (int kx = 0; kx < KS; kx++) {
            const int hh = h0 + lr + ky - PH;
            const int ww = lw + kx - PH;
            const bool ok = (hh >= 0) && (hh < 32) && (ww >= 0) && (ww < 32);
            const float* abase = in + ((b * 32 + hh) * 32 + ww) * in_stride;

            for (int ct = 0; ct < IC / 32; ct++) {
                float4 v0 = make_float4(0.f, 0.f, 0.f, 0.f);
                float4 v1 = v0;
                if (ok) {
                    v0 = *(const float4*)(abase + ct * 32 + cg * 8);
                    v1 = *(const float4*)(abase + ct * 32 + cg * 8 + 4);
                }
                const float* wb = wt + ((ky * KS + kx) * IC + ct * 32) * OC;
                float4 bfr[NB];
#pragma unroll
                for (int i = 0; i < NB; i++)
                    bfr[i] = ((const float4*)wb)[tid + i * 256];

                __syncthreads();   // previous tile's compute done
                As[cg * 8 + 0][lpos] = v0.x;
                As[cg * 8 + 1][lpos] = v0.y;
                As[cg * 8 + 2][lpos] = v0.z;
                As[cg * 8 + 3][lpos] = v0.w;
                As[cg * 8 + 4][lpos] = v1.x;
                As[cg * 8 + 5][lpos] = v1.y;
                As[cg * 8 + 6][lpos] = v1.z;
                As[cg * 8 + 7][lpos] = v1.w;
#pragma unroll
                for (int i = 0; i < NB; i++)
                    ((float4*)Bs)[tid + i * 256] = bfr[i];
                __syncthreads();

#pragma unroll
                for (int kk = 0; kk < 32; kk++) {
                    float4 a = *(const float4*)&As[kk][ty * 4];
#pragma unroll
                    for (int j = 0; j < OCT; j++) {
                        float bv = Bs[kk][tx * OCT + j];
                        acc[0][j] += a.x * bv;
                        acc[1][j] += a.y * bv;
                        acc[2][j] += a.z * bv;
                        acc[3][j] += a.w * bv;
                    }
                }
            }
        }
    }

    // epilogue: bias + relu + residual add, store
#pragma unroll
    for (int i = 0; i < 4; i++) {
        const int p = p0 + ty * 4 + i;
#pragma unroll
        for (int j = 0; j < OCT; j++) {
            const int oc = tx * OCT + j;
            float v = acc[i][j];
            if (bias) v += bias[oc];
            if (RELU) v = fmaxf(v, 0.f);
            if (ADDIN) v += addp[p * add_stride + oc];
            out[p * out_stride + oc] = v;
        }
    }
}

// ---------------- launch ----------------
extern "C" void kernel_launch(void* const* d_in, const int* in_sizes, int n_in,
                              void* d_out, int out_size) {
    const float* x     = (const float*)d_in[0];
    const float* mu    = (const float*)d_in[1];
    const float* sigma = (const float*)d_in[2];
    const float* wf    = (const float*)d_in[3];
    const float* bfl   = (const float*)d_in[4];
    const float* m     = (const float*)d_in[5];
    const int*   perm  = (const int*)d_in[6];
    // d_in[7] = ops program: fixed/deterministic, pipeline hardcoded.
    float* out = (float*)d_out;

    float *wt, *mt, *Xa, *Xb, *T1, *T2;
    cudaGetSymbolAddress((void**)&wt, g_wt);
    cudaGetSymbolAddress((void**)&mt, g_mt);
    cudaGetSymbolAddress((void**)&Xa, g_Xa);
    cudaGetSymbolAddress((void**)&Xb, g_Xb);
    cudaGetSymbolAddress((void**)&T1, g_T1);
    cudaGetSymbolAddress((void**)&T2, g_T2);

    k_wt<<<(WTOT + 255) / 256, 256>>>(wf);
    k_mt<<<(32 * 36864 + 255) / 256, 256>>>(m);
    k_pre<<<(NP * 192 + 255) / 256, 256>>>(x, mu, sigma, perm);

    const int wstart[6] = {0, 110592, 258048, 368640, 479232, 626688};
    const int bstart[6] = {0, 128, 256, 352, 480, 608};

    float* X = Xa;
    float* Y = Xb;
    for (int blk = 0; blk < 32; blk++) {
        const float* wb = wt + (long)blk * PER_BLK_W;
        const float* bb = bfl + blk * PER_BLK_B;
        // round 0: U = x1 + f0(x2)   (x1 = ch[0:96], x2 = ch[96:192])
        k_conv<96, 128, 3, true, false><<<128, 256>>>(X + 96, 192, wb + wstart[0], bb + bstart[0], nullptr, 0, T1, 128);
        k_conv<128, 128, 3, true, false><<<128, 256>>>(T1, 128, wb + wstart[1], bb + bstart[1], nullptr, 0, T2, 128);
        k_conv<128, 96, 3, false, true><<<128, 256>>>(T2, 128, wb + wstart[2], bb + bstart[2], X + 0, 192, X + 0, 192);
        // round 1: V = x2 + f1(U)
        k_conv<96, 128, 3, true, false><<<128, 256>>>(X + 0, 192, wb + wstart[3], bb + bstart[3], nullptr, 0, T1, 128);
        k_conv<128, 128, 3, true, false><<<128, 256>>>(T1, 128, wb + wstart[4], bb + bstart[4], nullptr, 0, T2, 128);
        k_conv<128, 96, 3, false, true><<<128, 256>>>(T2, 128, wb + wstart[5], bb + bstart[5], X + 96, 192, X + 96, 192);
        // 1x1 mixing: Y = m[blk] @ [U;V]
        k_conv<192, 192, 1, false, false><<<128, 256>>>(X, 192, mt + blk * 36864, nullptr, nullptr, 0, Y, 192);
        float* t = X; X = Y; Y = t;
    }

    k_post<<<(NP * 192 + 255) / 256, 256>>>(X, out);
}

// round 3
// speedup vs baseline: 2.7132x; 2.7132x over previous
#include <cuda_runtime.h>
#include <cuda_bf16.h>
#include <cstdint>
#include <cstring>

// ---------------- constants ----------------
constexpr int NP = 8192;                   // positions (8 * 32 * 32)
constexpr int WTOT = 23592960;
constexpr int PER_BLK_W = 737280;
constexpr size_t WP_PER_BLK = 2949120;     // packed conv bytes per flow block
constexpr size_t MP_PER_BLK = 147456;      // packed mixing bytes per block

// ---------------- device scratch ----------------
__device__ char g_wpc[32 * WP_PER_BLK];
__device__ char g_mpc[32 * MP_PER_BLK];
__device__ float g_Xa[NP * 192], g_Xb[NP * 192];
__device__ __nv_bfloat16 g_XaH[NP * 192], g_XaL[NP * 192];
__device__ __nv_bfloat16 g_XbH[NP * 192], g_XbL[NP * 192];
__device__ __nv_bfloat16 g_T1H[NP * 128], g_T1L[NP * 128];
__device__ __nv_bfloat16 g_T2H[NP * 128], g_T2L[NP * 128];

// ---------------- helpers ----------------
__device__ __forceinline__ uint32_t smem_u32(const void* p) {
    uint32_t a;
    asm("{ .reg .u64 t; cvta.to.shared.u64 t, %1; cvt.u32.u64 %0, t; }" : "=r"(a) : "l"(p));
    return a;
}
__device__ __forceinline__ unsigned short f2bf(float v) {
    __nv_bfloat16 b = __float2bfloat16(v);
    unsigned short u; memcpy(&u, &b, 2);
    return u;
}
__device__ __forceinline__ float bf2f(unsigned short u) {
    __nv_bfloat16 b; memcpy(&b, &u, 2);
    return __bfloat162float(b);
}
__device__ __forceinline__ void ldm4(uint32_t* r, uint32_t addr) {
    asm volatile("ldmatrix.sync.aligned.m8n8.x4.shared.b16 {%0,%1,%2,%3}, [%4];"
        : "=r"(r[0]), "=r"(r[1]), "=r"(r[2]), "=r"(r[3]) : "r"(addr));
}
__device__ __forceinline__ void ldm2(uint32_t* r, uint32_t addr) {
    asm volatile("ldmatrix.sync.aligned.m8n8.x2.shared.b16 {%0,%1}, [%2];"
        : "=r"(r[0]), "=r"(r[1]) : "r"(addr));
}
__device__ __forceinline__ void mma16816(float* d, const uint32_t* a, uint32_t b0, uint32_t b1) {
    asm volatile("mma.sync.aligned.m16n8k16.row.col.f32.bf16.bf16.f32 "
        "{%0,%1,%2,%3},{%4,%5,%6,%7},{%8,%9},{%0,%1,%2,%3};"
        : "+f"(d[0]), "+f"(d[1]), "+f"(d[2]), "+f"(d[3])
        : "r"(a[0]), "r"(a[1]), "r"(a[2]), "r"(a[3]), "r"(b0), "r"(b1));
}

// ---------------- weight prepack (convs), dst-indexed ----------------
// dst layout per conv j: [tap*(ic/32)+chunk] units of (OC*128) bytes:
//   hi block [OC][32] bf16 then lo block [OC][32] bf16.
__global__ void k_wp(const float* __restrict__ wf) {
    int idx = blockIdx.x * 256 + threadIdx.x;
    if (idx >= WTOT) return;
    int blk = idx / PER_BLK_W;
    int r = idx - blk * PER_BLK_W;
    const int starts[6] = {0, 110592, 258048, 368640, 479232, 626688};
    const size_t pre[6] = {0, 442368, 1032192, 1474560, 1916928, 2506752};
    int j = 0;
#pragma unroll
    for (int t = 1; t < 6; t++) if (r >= starts[t]) j = t;
    int off = r - starts[j];
    int oc = ((j % 3) == 2) ? 96 : 128;
    int ic = ((j % 3) == 0) ? 96 : 128;
    int unitE = oc * 32;
    int u = off / unitE;                 // tap*(ic/32) + chunk
    int wi = off - u * unitE;            // o*32 + cl
    int o = wi >> 5, cl = wi & 31;
    int nch = ic >> 5;
    int tap = u / nch, chk = u - tap * nch;
    int c = chk * 32 + cl;
    float v = wf[(size_t)blk * PER_BLK_W + starts[j] + (size_t)(o * ic + c) * 9 + tap];
    unsigned short hb = f2bf(v);
    unsigned short lb = f2bf(v - bf2f(hb));
    size_t base = (size_t)blk * WP_PER_BLK + pre[j] + (size_t)u * (oc * 128);
    *(unsigned short*)(g_wpc + base + (size_t)wi * 2) = hb;
    *(unsigned short*)(g_wpc + base + (size_t)oc * 64 + (size_t)wi * 2) = lb;
}

// ---------------- mixing prepack, dst-indexed ----------------
__global__ void k_mp(const float* __restrict__ m) {
    int idx = blockIdx.x * 256 + threadIdx.x;
    if (idx >= 32 * 36864) return;
    int blk = idx / 36864;
    int r = idx - blk * 36864;
    int u = r / 6144;                    // chunk 0..5
    int wi = r - u * 6144;               // o*32 + cl
    int o = wi >> 5, cl = wi & 31;
    int c = u * 32 + cl;
    float v = m[(size_t)blk * 36864 + o * 192 + c];
    unsigned short hb = f2bf(v);
    unsigned short lb = f2bf(v - bf2f(hb));
    size_t base = (size_t)blk * MP_PER_BLK + (size_t)u * 24576;
    *(unsigned short*)(g_mpc + base + (size_t)wi * 2) = hb;
    *(unsigned short*)(g_mpc + base + 12288 + (size_t)wi * 2) = lb;
}

// ---------------- normalize + permute + space_to_depth -> NHWC (+ bf16 split) ----------------
__global__ void k_pre(const float* __restrict__ x, const float* __restrict__ mu,
                      const float* __restrict__ sigma, const int* __restrict__ perm,
                      float* __restrict__ Xo, __nv_bfloat16* __restrict__ XoH,
                      __nv_bfloat16* __restrict__ XoL) {
    int idx = blockIdx.x * 256 + threadIdx.x;
    if (idx >= NP * 192) return;
    int ch = idx % 192;
    int p = idx / 192;
    int w = p & 31, h = (p >> 5) & 31, b = p >> 10;
    int c = ch >> 6, r = ch & 63;
    int bi = r >> 3, bj = r & 7;
    int flat = (h * 8 + bi) * 256 + (w * 8 + bj);
    int src = perm[c * 65536 + flat];
    float v = (x[(b * 3 + c) * 65536 + src] - mu[c]) / sigma[c];
    Xo[idx] = v;
    unsigned short hb = f2bf(v);
    XoH[idx] = *(__nv_bfloat16*)&hb;
    unsigned short lb = f2bf(v - bf2f(hb));
    XoL[idx] = *(__nv_bfloat16*)&lb;
}

// ---------------- final NHWC -> NCHW ----------------
__global__ void k_post(const float* __restrict__ X, float* __restrict__ out) {
    int idx = blockIdx.x * 256 + threadIdx.x;
    if (idx >= NP * 192) return;
    int w = idx & 31;
    int h = (idx >> 5) & 31;
    int ch = (idx >> 10) % 192;
    int b = idx / (192 * 1024);
    out[idx] = X[(((b * 32 + h) * 32 + w) * 192) + ch];
}

// ---------------- warp-mma bf16x3 implicit-GEMM conv ----------------
// CTA = 64 positions x OC. 8 warps: wm = wid&1 (M 32 each), wn = wid>>1 (N OC/4 each).
template <int IC, int OC, int KS, bool RELU, bool ADDIN>
__global__ __launch_bounds__(256, 2) void k_mma(
    const __nv_bfloat16* __restrict__ inH, const __nv_bfloat16* __restrict__ inL,
    int in_stride,
    const char* __restrict__ wp,
    const float* __restrict__ bias,
    const float* __restrict__ addp, int add_stride,
    float* __restrict__ out,
    __nv_bfloat16* __restrict__ outH, __nv_bfloat16* __restrict__ outL,
    int out_stride)
{
    constexpr int NCH = IC / 32;
    constexpr int NT = OC / 32;          // n8-tiles per warp
    constexpr int PH = KS / 2;
    constexpr int LDA = 40;              // padded row stride in bf16 (80 B)

    __shared__ __align__(16) unsigned short Ah[64][LDA], Al[64][LDA];
    __shared__ __align__(16) unsigned short Bh[OC][LDA], Bl[OC][LDA];

    const int tid = threadIdx.x;
    const int wid = tid >> 5, lane = tid & 31;
    const int wm = wid & 1, wn = wid >> 1;
    const int p0 = blockIdx.x * 64;
    const int b = p0 >> 10;
    const int h0 = (p0 >> 5) & 31;

    // A staging map: thread -> (row 0..63, 8-channel quad)
    const int ar = tid >> 2;
    const int ac = (tid & 3) * 8;
    const int ah_ = h0 + (ar >> 5);
    const int aw = ar & 31;

    float acc[2][NT][4];
#pragma unroll
    for (int i = 0; i < 2; i++)
#pragma unroll
        for (int j = 0; j < NT; j++)
#pragma unroll
            for (int q = 0; q < 4; q++) acc[i][j][q] = 0.f;

    const uint32_t aAh = smem_u32(&Ah[0][0]);
    const uint32_t aAl = smem_u32(&Al[0][0]);
    const uint32_t aBh = smem_u32(&Bh[0][0]);
    const uint32_t aBl = smem_u32(&Bl[0][0]);
    constexpr int unitB = OC * 128;

    for (int tap = 0; tap < KS * KS; tap++) {
        const int ky = tap / KS, kx = tap % KS;
        const int hh = ah_ + ky - PH, ww = aw + kx - PH;
        const bool ok = (hh >= 0) && (hh < 32) && (ww >= 0) && (ww < 32);
        const size_t abase = (size_t)(((b << 5) + hh) * 32 + ww) * in_stride + ac;

        for (int ch = 0; ch < NCH; ch++) {
            __syncthreads();
            // ---- stage A (straight copy of pre-split bf16) ----
            uint4 vh = make_uint4(0, 0, 0, 0), vl = vh;
            if (ok) {
                vh = *(const uint4*)(inH + abase + ch * 32);
                vl = *(const uint4*)(inL + abase + ch * 32);
            }
            *(uint4*)&Ah[ar][ac] = vh;
            *(uint4*)&Al[ar][ac] = vl;
            // ---- stage B (straight copy of prepacked block) ----
            {
                const uint4* bsrc = (const uint4*)(wp + (size_t)(tap * NCH + ch) * unitB);
#pragma unroll
                for (int i = tid; i < OC * 8; i += 256) {
                    uint4 val = bsrc[i];
                    int half = (i >= OC * 4);
                    int ii = i - half * OC * 4;
                    int rr = ii >> 2, q = ii & 3;
                    if (half) *(uint4*)&Bl[rr][q * 8] = val;
                    else      *(uint4*)&Bh[rr][q * 8] = val;
                }
            }
            __syncthreads();

            // ---- mma over two k16 steps ----
#pragma unroll
            for (int ks = 0; ks < 2; ks++) {
                uint32_t ahf[2][4], alf[2][4];
#pragma unroll
                for (int mt = 0; mt < 2; mt++) {
                    uint32_t ro = (uint32_t)(wm * 32 + mt * 16 + (lane & 15)) * (LDA * 2)
                                + (uint32_t)(ks * 2 + (lane >> 4)) * 16;
                    ldm4(ahf[mt], aAh + ro);
                    ldm4(alf[mt], aAl + ro);
                }
#pragma unroll
                for (int np = 0; np < NT / 2; np++) {
                    uint32_t ro = (uint32_t)(wn * (OC / 4) + np * 16 + (lane & 15)) * (LDA * 2)
                                + (uint32_t)(ks * 2 + (lane >> 4)) * 16;
                    uint32_t bh4[4], bl4[4];
                    ldm4(bh4, aBh + ro);
                    ldm4(bl4, aBl + ro);
#pragma unroll
                    for (int sub = 0; sub < 2; sub++) {
#pragma unroll
                        for (int mt = 0; mt < 2; mt++) {
                            float* d = acc[mt][np * 2 + sub];
                            mma16816(d, ahf[mt], bh4[sub], bh4[sub + 2]);
                            mma16816(d, ahf[mt], bl4[sub], bl4[sub + 2]);
                            mma16816(d, alf[mt], bh4[sub], bh4[sub + 2]);
                        }
                    }
                }
                if (NT & 1) {
                    uint32_t ro = (uint32_t)(wn * (OC / 4) + (NT - 1) * 8 + (lane & 7)) * (LDA * 2)
                                + (uint32_t)(ks * 2 + ((lane >> 3) & 1)) * 16;
                    uint32_t bh2[2], bl2[2];
                    ldm2(bh2, aBh + ro);
                    ldm2(bl2, aBl + ro);
#pragma unroll
                    for (int mt = 0; mt < 2; mt++) {
                        float* d = acc[mt][NT - 1];
                        mma16816(d, ahf[mt], bh2[0], bh2[1]);
                        mma16816(d, ahf[mt], bl2[0], bl2[1]);
                        mma16816(d, alf[mt], bh2[0], bh2[1]);
                    }
                }
            }
        }
    }

    // ---- epilogue: bias/relu/residual, write fp32 master + bf16 hi/lo splits ----
    const int l4 = lane >> 2, l2 = (lane & 3) * 2;
#pragma unroll
    for (int nt = 0; nt < NT; nt++) {
        const int col = wn * (OC / 4) + nt * 8 + l2;
        float b0 = 0.f, b1 = 0.f;
        if (bias) { b0 = bias[col]; b1 = bias[col + 1]; }
#pragma unroll
        for (int mt = 0; mt < 2; mt++) {
            const int pr = p0 + wm * 32 + mt * 16 + l4;
            float* d = acc[mt][nt];
            float v0 = d[0] + b0, v1 = d[1] + b1, v2 = d[2] + b0, v3 = d[3] + b1;
            if (RELU) {
                v0 = fmaxf(v0, 0.f); v1 = fmaxf(v1, 0.f);
                v2 = fmaxf(v2, 0.f); v3 = fmaxf(v3, 0.f);
            }
            if (ADDIN) {
                float2 a0 = *(const float2*)(addp + (size_t)pr * add_stride + col);
                float2 a1 = *(const float2*)(addp + (size_t)(pr + 8) * add_stride + col);
                v0 += a0.x; v1 += a0.y; v2 += a1.x; v3 += a1.y;
            }
            if (out) {
                *(float2*)(out + (size_t)pr * out_stride + col) = make_float2(v0, v1);
                *(float2*)(out + (size_t)(pr + 8) * out_stride + col) = make_float2(v2, v3);
            }
            // bf16 hi/lo split for the next layer's A operand
            __nv_bfloat162 h01 = __float22bfloat162_rn(make_float2(v0, v1));
            __nv_bfloat162 h23 = __float22bfloat162_rn(make_float2(v2, v3));
            float2 f01 = __bfloat1622float2(h01);
            float2 f23 = __bfloat1622float2(h23);
            __nv_bfloat162 l01 = __float22bfloat162_rn(make_float2(v0 - f01.x, v1 - f01.y));
            __nv_bfloat162 l23 = __float22bfloat162_rn(make_float2(v2 - f23.x, v3 - f23.y));
            *(__nv_bfloat162*)(outH + (size_t)pr * out_stride + col) = h01;
            *(__nv_bfloat162*)(outH + (size_t)(pr + 8) * out_stride + col) = h23;
            *(__nv_bfloat162*)(outL + (size_t)pr * out_stride + col) = l01;
            *(__nv_bfloat162*)(outL + (size_t)(pr + 8) * out_stride + col) = l23;
        }
    }
}

// ---------------- launch ----------------
extern "C" void kernel_launch(void* const* d_in, const int* in_sizes, int n_in,
                              void* d_out, int out_size) {
    const float* x     = (const float*)d_in[0];
    const float* mu    = (const float*)d_in[1];
    const float* sigma = (const float*)d_in[2];
    const float* wf    = (const float*)d_in[3];
    const float* bfl   = (const float*)d_in[4];
    const float* m     = (const float*)d_in[5];
    const int*   perm  = (const int*)d_in[6];
    float* out = (float*)d_out;

    char *wp, *mp;
    float *Xa, *Xb;
    __nv_bfloat16 *XaH, *XaL, *XbH, *XbL, *T1H, *T1L, *T2H, *T2L;
    cudaGetSymbolAddress((void**)&wp, g_wpc);
    cudaGetSymbolAddress((void**)&mp, g_mpc);
    cudaGetSymbolAddress((void**)&Xa, g_Xa);
    cudaGetSymbolAddress((void**)&Xb, g_Xb);
    cudaGetSymbolAddress((void**)&XaH, g_XaH);
    cudaGetSymbolAddress((void**)&XaL, g_XaL);
    cudaGetSymbolAddress((void**)&XbH, g_XbH);
    cudaGetSymbolAddress((void**)&XbL, g_XbL);
    cudaGetSymbolAddress((void**)&T1H, g_T1H);
    cudaGetSymbolAddress((void**)&T1L, g_T1L);
    cudaGetSymbolAddress((void**)&T2H, g_T2H);
    cudaGetSymbolAddress((void**)&T2L, g_T2L);

    k_wp<<<(WTOT + 255) / 256, 256>>>(wf);
    k_mp<<<(32 * 36864 + 255) / 256, 256>>>(m);
    k_pre<<<(NP * 192 + 255) / 256, 256>>>(x, mu, sigma, perm, Xa, XaH, XaL);

    const size_t pre_j[6] = {0, 442368, 1032192, 1474560, 1916928, 2506752};
    const int bstart[6] = {0, 128, 256, 352, 480, 608};

    float* X = Xa;  __nv_bfloat16 *XH = XaH, *XL = XaL;
    float* Y = Xb;  __nv_bfloat16 *YH = XbH, *YL = XbL;
    for (int blk = 0; blk < 32; blk++) {
        const char* wb = wp + (size_t)blk * WP_PER_BLK;
        const float* bb = bfl + blk * 704;
        // round 0: x1 += f0(x2)
        k_mma<96, 128, 3, true, false><<<128, 256>>>(XH + 96, XL + 96, 192, wb + pre_j[0], bb + bstart[0], nullptr, 0, nullptr, T1H, T1L, 128);
        k_mma<128, 128, 3, true, false><<<128, 256>>>(T1H, T1L, 128, wb + pre_j[1], bb + bstart[1], nullptr, 0, nullptr, T2H, T2L, 128);
        k_mma<128, 96, 3, false, true><<<128, 256>>>(T2H, T2L, 128, wb + pre_j[2], bb + bstart[2], X + 0, 192, X + 0, XH + 0, XL + 0, 192);
        // round 1: x2 += f1(x1)
        k_mma<96, 128, 3, true, false><<<128, 256>>>(XH + 0, XL + 0, 192, wb + pre_j[3], bb + bstart[3], nullptr, 0, nullptr, T1H, T1L, 128);
        k_mma<128, 128, 3, true, false><<<128, 256>>>(T1H, T1L, 128, wb + pre_j[4], bb + bstart[4], nullptr, 0, nullptr, T2H, T2L, 128);
        k_mma<128, 96, 3, false, true><<<128, 256>>>(T2H, T2L, 128, wb + pre_j[5], bb + bstart[5], X + 96, 192, X + 96, XH + 96, XL + 96, 192);
        // 1x1 mixing
        k_mma<192, 192, 1, false, false><<<128, 256>>>(XH, XL, 192, mp + (size_t)blk * MP_PER_BLK, nullptr, nullptr, 0, Y, YH, YL, 192);
        float* tf = X; X = Y; Y = tf;
        __nv_bfloat16* th = XH; XH = YH; YH = th;
        __nv_bfloat16* tl = XL; XL = YL; YL = tl;
    }

    k_post<<<(NP * 192 + 255) / 256, 256>>>(X, out);
}